// round 1
// baseline (speedup 1.0000x reference)
#include <cuda_runtime.h>
#include <cuda_bf16.h>
#include <mma.h>
using namespace nvcuda;

#define T_ 8
#define N_ 1024
#define D_ 128
static constexpr float SCALE = 0.08838834764831845f; // 1/sqrt(128)

// ---- scratch (allocation-free rule: __device__ globals) ----
__device__ __align__(16) __nv_bfloat16 g_Xh[T_ * N_ * D_];   // 2 MB
__device__ __align__(16) float         g_S [T_ * N_ * N_];   // 32 MB raw scores
__device__ __align__(16) __nv_bfloat16 g_Ah[T_ * N_ * N_];   // 16 MB attention bf16
__device__ __align__(16) float         g_Y [T_ * N_ * D_];   // 4 MB node features
__device__ __align__(16) float         g_SW[N_ * T_ * T_];   // 256 KB sigmoid weights

// ---------------- K0: fp32 -> bf16 cast ----------------
__global__ void k_cast(const float* __restrict__ x) {
    int i = blockIdx.x * blockDim.x + threadIdx.x;
    if (i < T_ * N_ * D_) g_Xh[i] = __float2bfloat16(x[i]);
}

// ---------------- K1: S_t = X_t X_t^T (raw, unscaled) ----------------
// block tile 64x64, K=128 fully staged in smem, 4 warps (2x2), warp tile 32x32
__global__ void k_qk() {
    int t  = blockIdx.z;
    int m0 = blockIdx.y * 64;
    int n0 = blockIdx.x * 64;
    __shared__ __align__(16) __nv_bfloat16 As[64][136];
    __shared__ __align__(16) __nv_bfloat16 Bs[64][136];
    const __nv_bfloat16* Xt = g_Xh + t * N_ * D_;
    int tid = threadIdx.x;

    #pragma unroll
    for (int k = 0; k < 8; k++) {
        int idx = tid + k * 128;
        int r = idx >> 4, c = (idx & 15) * 8;
        *(uint4*)&As[r][c] = *(const uint4*)&Xt[(m0 + r) * D_ + c];
        *(uint4*)&Bs[r][c] = *(const uint4*)&Xt[(n0 + r) * D_ + c];
    }
    __syncthreads();

    int w  = tid >> 5;
    int wm = (w >> 1) * 32, wn = (w & 1) * 32;

    wmma::fragment<wmma::accumulator, 16, 16, 16, float> acc[2][2];
    #pragma unroll
    for (int mm = 0; mm < 2; mm++)
        #pragma unroll
        for (int nn = 0; nn < 2; nn++) wmma::fill_fragment(acc[mm][nn], 0.0f);

    #pragma unroll
    for (int k0 = 0; k0 < 128; k0 += 16) {
        wmma::fragment<wmma::matrix_a, 16, 16, 16, __nv_bfloat16, wmma::row_major> a[2];
        wmma::fragment<wmma::matrix_b, 16, 16, 16, __nv_bfloat16, wmma::col_major> b[2];
        wmma::load_matrix_sync(a[0], &As[wm][k0], 136);
        wmma::load_matrix_sync(a[1], &As[wm + 16][k0], 136);
        wmma::load_matrix_sync(b[0], &Bs[wn][k0], 136);
        wmma::load_matrix_sync(b[1], &Bs[wn + 16][k0], 136);
        #pragma unroll
        for (int mm = 0; mm < 2; mm++)
            #pragma unroll
            for (int nn = 0; nn < 2; nn++)
                wmma::mma_sync(acc[mm][nn], a[mm], b[nn], acc[mm][nn]);
    }

    float* Sout = g_S + (size_t)t * N_ * N_;
    #pragma unroll
    for (int mm = 0; mm < 2; mm++)
        #pragma unroll
        for (int nn = 0; nn < 2; nn++)
            wmma::store_matrix_sync(&Sout[(m0 + wm + mm * 16) * N_ + n0 + wn + nn * 16],
                                    acc[mm][nn], N_, wmma::mem_row_major);
}

// ---------------- K2: mask + scale + row softmax -> bf16 attention ----------------
__global__ void k_softmax(const int* __restrict__ adj) {
    int b = blockIdx.x;            // 8192 rows
    int t = b >> 10, i = b & 1023;
    const float* Srow = g_S + ((size_t)t * N_ + i) * N_;
    const int*   arow = adj + i * N_;
    __nv_bfloat16* Aout = g_Ah + ((size_t)t * N_ + i) * N_;

    int tid = threadIdx.x;         // 256 threads, 4 cols each
    float4 s4 = ((const float4*)Srow)[tid];
    int4   a4 = ((const int4*)arow)[tid];
    float v0 = (a4.x > 0) ? s4.x * SCALE : -1e12f;
    float v1 = (a4.y > 0) ? s4.y * SCALE : -1e12f;
    float v2 = (a4.z > 0) ? s4.z * SCALE : -1e12f;
    float v3 = (a4.w > 0) ? s4.w * SCALE : -1e12f;

    __shared__ float shMax[8], shSum[8];
    int w = tid >> 5, l = tid & 31;

    float mx = fmaxf(fmaxf(v0, v1), fmaxf(v2, v3));
    #pragma unroll
    for (int o = 16; o; o >>= 1) mx = fmaxf(mx, __shfl_xor_sync(~0u, mx, o));
    if (l == 0) shMax[w] = mx;
    __syncthreads();
    if (w == 0) {
        float x = (l < 8) ? shMax[l] : -1e38f;
        #pragma unroll
        for (int o = 4; o; o >>= 1) x = fmaxf(x, __shfl_xor_sync(~0u, x, o));
        if (l == 0) shMax[0] = x;
    }
    __syncthreads();
    mx = shMax[0];

    float e0 = __expf(v0 - mx), e1 = __expf(v1 - mx);
    float e2 = __expf(v2 - mx), e3 = __expf(v3 - mx);
    float sm = e0 + e1 + e2 + e3;
    #pragma unroll
    for (int o = 16; o; o >>= 1) sm += __shfl_xor_sync(~0u, sm, o);
    if (l == 0) shSum[w] = sm;
    __syncthreads();
    if (w == 0) {
        float x = (l < 8) ? shSum[l] : 0.0f;
        #pragma unroll
        for (int o = 4; o; o >>= 1) x += __shfl_xor_sync(~0u, x, o);
        if (l == 0) shSum[0] = x;
    }
    __syncthreads();
    float inv = 1.0f / shSum[0];

    __nv_bfloat162* o2 = (__nv_bfloat162*)Aout;
    o2[tid * 2]     = __floats2bfloat162_rn(e0 * inv, e1 * inv);
    o2[tid * 2 + 1] = __floats2bfloat162_rn(e2 * inv, e3 * inv);
}

// ---------------- K3: Y_t = A_t @ X_t ----------------
// block tile 64x64(out), K=1024 in chunks of 64
__global__ void k_av() {
    int t  = blockIdx.z;
    int m0 = blockIdx.y * 64;
    int n0 = blockIdx.x * 64;   // n0 in {0, 64}
    __shared__ __align__(16) __nv_bfloat16 As[64][72];
    __shared__ __align__(16) __nv_bfloat16 Bs[64][72];
    const __nv_bfloat16* At = g_Ah + (size_t)t * N_ * N_;
    const __nv_bfloat16* Xt = g_Xh + (size_t)t * N_ * D_;
    int tid = threadIdx.x;
    int w  = tid >> 5;
    int wm = (w >> 1) * 32, wn = (w & 1) * 32;

    wmma::fragment<wmma::accumulator, 16, 16, 16, float> acc[2][2];
    #pragma unroll
    for (int mm = 0; mm < 2; mm++)
        #pragma unroll
        for (int nn = 0; nn < 2; nn++) wmma::fill_fragment(acc[mm][nn], 0.0f);

    for (int k0 = 0; k0 < N_; k0 += 64) {
        __syncthreads();
        #pragma unroll
        for (int q = 0; q < 4; q++) {
            int idx = tid + q * 128;
            int r = idx >> 3, c = (idx & 7) * 8;
            *(uint4*)&As[r][c] = *(const uint4*)&At[(m0 + r) * N_ + k0 + c];
            *(uint4*)&Bs[r][c] = *(const uint4*)&Xt[(k0 + r) * D_ + n0 + c];
        }
        __syncthreads();

        #pragma unroll
        for (int kk = 0; kk < 4; kk++) {
            wmma::fragment<wmma::matrix_a, 16, 16, 16, __nv_bfloat16, wmma::row_major> a[2];
            wmma::fragment<wmma::matrix_b, 16, 16, 16, __nv_bfloat16, wmma::row_major> b[2];
            wmma::load_matrix_sync(a[0], &As[wm][kk * 16], 72);
            wmma::load_matrix_sync(a[1], &As[wm + 16][kk * 16], 72);
            wmma::load_matrix_sync(b[0], &Bs[kk * 16][wn], 72);
            wmma::load_matrix_sync(b[1], &Bs[kk * 16][wn + 16], 72);
            #pragma unroll
            for (int mm = 0; mm < 2; mm++)
                #pragma unroll
                for (int nn = 0; nn < 2; nn++)
                    wmma::mma_sync(acc[mm][nn], a[mm], b[nn], acc[mm][nn]);
        }
    }

    float* Yout = g_Y + (size_t)t * N_ * D_;
    #pragma unroll
    for (int mm = 0; mm < 2; mm++)
        #pragma unroll
        for (int nn = 0; nn < 2; nn++)
            wmma::store_matrix_sync(&Yout[(m0 + wm + mm * 16) * D_ + n0 + wn + nn * 16],
                                    acc[mm][nn], D_, wmma::mem_row_major);
}

// ---------------- K4: per node 8x8 Gram + sigmoid (fp32) ----------------
__global__ void k_temp() {
    int gwarp = (blockIdx.x * blockDim.x + threadIdx.x) >> 5;
    int lane  = threadIdx.x & 31;
    if (gwarp >= N_) return;
    int n = gwarp;

    float y[T_][4];
    #pragma unroll
    for (int t = 0; t < T_; t++)
        #pragma unroll
        for (int q = 0; q < 4; q++)
            y[t][q] = g_Y[((size_t)t * N_ + n) * D_ + q * 32 + lane];

    float G[64];
    #pragma unroll
    for (int p = 0; p < 64; p++) G[p] = 0.0f;
    #pragma unroll
    for (int t = 0; t < T_; t++)
        #pragma unroll
        for (int s = 0; s < T_; s++)
            #pragma unroll
            for (int q = 0; q < 4; q++)
                G[t * 8 + s] = fmaf(y[t][q], y[s][q], G[t * 8 + s]);

    #pragma unroll
    for (int p = 0; p < 64; p++) {
        float v = G[p];
        #pragma unroll
        for (int o = 16; o; o >>= 1) v += __shfl_xor_sync(~0u, v, o);
        G[p] = v;
    }

    #pragma unroll
    for (int k = 0; k < 2; k++) {
        int p = lane + k * 32;
        float x = G[p] * SCALE;
        g_SW[n * 64 + p] = 1.0f / (1.0f + __expf(-x));
    }
}

// ---------------- K5: broadcast-expand 256MB write ----------------
// out[s*N + j, t*N + i] = sw[j, t, s]   (independent of i)
__global__ void k_expand(float* __restrict__ out) {
    int r = blockIdx.x;            // 8192 rows
    int s = r >> 10, j = r & 1023;
    int tid = threadIdx.x;         // 256 threads
    float4* orow = (float4*)(out + (size_t)r * 8192);
    #pragma unroll
    for (int t = 0; t < T_; t++) {
        float v = g_SW[j * 64 + t * 8 + s];
        orow[t * 256 + tid] = make_float4(v, v, v, v);
    }
}

extern "C" void kernel_launch(void* const* d_in, const int* in_sizes, int n_in,
                              void* d_out, int out_size) {
    const float* raw = (const float*)d_in[0];
    const int*   adj = (const int*)d_in[1];
    float*       out = (float*)d_out;

    k_cast<<<(T_ * N_ * D_ + 255) / 256, 256>>>(raw);
    k_qk<<<dim3(16, 16, T_), 128>>>();
    k_softmax<<<T_ * N_, 256>>>(adj);
    k_av<<<dim3(2, 16, T_), 128>>>();
    k_temp<<<N_ / 8, 256>>>();
    k_expand<<<T_ * N_, 256>>>(out);
}